// round 7
// baseline (speedup 1.0000x reference)
#include <cuda_runtime.h>
#include <stdint.h>

// Problem constants (fixed by the dataset)
#define NPTS      32768
#define NKERN     4
#define GRID      16
#define C_IN      64
#define C_OUT     64
#define NCELLS    (NKERN * GRID * GRID * GRID)   // 16384
#define NENT      (NPTS * 8)                     // 262144

// ---------------------------------------------------------------------------
// Device scratch (static __device__ globals: allowed; no cudaMalloc anywhere)
// NOTE: g_counts is zero on first use (static zero-init) and re-zeroed at the
// END of each call (tail of k_scatter), so every call sees a clean histogram.
// ---------------------------------------------------------------------------
__device__ unsigned g_counts[NCELLS];
__device__ unsigned g_offsets[NCELLS + 1];
__device__ unsigned g_cursor[NCELLS];
__device__ unsigned g_cells[NENT];     // cell id per (point,corner) entry
__device__ float    g_wts[NENT];       // trilinear weight per entry
__device__ unsigned g_sorted[NENT];    // entry ids grouped by cell
__device__ float    g_swts[NENT];      // weights in sorted order (coalesced read)
__device__ float    g_contrib[(size_t)NENT * C_OUT];  // 67MB staging (deterministic)

// packed f32x2 FMA: d = a*b + d  (SASS FFMA2 — 2 fp32 MACs per lane per issue)
__device__ __forceinline__ void ffma2(unsigned long long& d,
                                      unsigned long long a,
                                      unsigned long long b) {
    asm("fma.rn.f32x2 %0, %1, %2, %0;" : "+l"(d) : "l"(a), "l"(b));
}
__device__ __forceinline__ unsigned long long bcast2(float v) {
    unsigned long long r;
    asm("mov.b64 %0, {%1, %1};" : "=l"(r) : "f"(v));
    return r;
}
__device__ __forceinline__ float2 unpack2(unsigned long long v) {
    float2 r;
    asm("mov.b64 {%0, %1}, %2;" : "=f"(r.x), "=f"(r.y) : "l"(v));
    return r;
}

// ---------------------------------------------------------------------------
// K1: per-point corner cells + weights, histogram cells
// ---------------------------------------------------------------------------
__global__ void k_prep(const int* __restrict__ pidx,
                       const float* __restrict__ pos) {
    int n = blockIdx.x * blockDim.x + threadIdx.x;
    if (n >= NPTS) return;

    float lx = pos[n * 3 + 0] * (float)GRID - 0.5f;
    float ly = pos[n * 3 + 1] * (float)GRID - 0.5f;
    float lz = pos[n * 3 + 2] * (float)GRID - 0.5f;
    float fx = floorf(lx), fy = floorf(ly), fz = floorf(lz);
    float cwx = lx - fx, cwy = ly - fy, cwz = lz - fz;
    float fwx = 1.f - cwx, fwy = 1.f - cwy, fwz = 1.f - cwz;
    int ix = (int)fx, iy = (int)fy, iz = (int)fz;   // may be -1..15
    int pi = pidx[n];

    #pragma unroll
    for (int k = 0; k < 8; k++) {
        int bx = k & 1, by = (k >> 1) & 1, bz = (k >> 2) & 1;
        int jx = min(max(ix + bx, 0), GRID - 1);
        int jy = min(max(iy + by, 0), GRID - 1);
        int jz = min(max(iz + bz, 0), GRID - 1);
        float w = (bx ? cwx : fwx) * (by ? cwy : fwy) * (bz ? cwz : fwz);
        // reference indexes kernels[pidx, idx_z, idx_y, idx_x]
        unsigned cell = (((unsigned)pi * GRID + jz) * GRID + jy) * GRID + jx;
        g_cells[n * 8 + k] = cell;
        g_wts[n * 8 + k] = w;
        atomicAdd(&g_counts[cell], 1u);
    }
}

// ---------------------------------------------------------------------------
// K2: single-block exclusive scan of 16384 counts (512 thr x 32 elems)
// ---------------------------------------------------------------------------
__global__ void k_scan() {
    __shared__ unsigned part[512];
    int t = threadIdx.x;
    unsigned sum = 0;
    #pragma unroll 4
    for (int i = 0; i < 32; i++) sum += g_counts[t * 32 + i];
    part[t] = sum;
    __syncthreads();
    for (int off = 1; off < 512; off <<= 1) {
        unsigned v = 0;
        if (t >= off) v = part[t - off];
        __syncthreads();
        if (t >= off) part[t] += v;
        __syncthreads();
    }
    unsigned run = (t == 0) ? 0u : part[t - 1];
    #pragma unroll 4
    for (int i = 0; i < 32; i++) {
        int idx = t * 32 + i;
        g_offsets[idx] = run;
        g_cursor[idx] = run;
        run += g_counts[idx];
    }
    if (t == 511) g_offsets[NCELLS] = run;   // == NENT
}

// ---------------------------------------------------------------------------
// K3: scatter entries into cell-grouped order; also stage sorted weights and
//     re-zero the histogram for the NEXT call (counts are dead after k_scan).
// ---------------------------------------------------------------------------
__global__ void k_scatter() {
    int e = blockIdx.x * blockDim.x + threadIdx.x;
    if (e < NCELLS) g_counts[e] = 0u;            // reset for next call
    if (e >= NENT) return;
    unsigned cell = g_cells[e];
    unsigned slot = atomicAdd(&g_cursor[cell], 1u);
    g_sorted[slot] = (unsigned)e;
    g_swts[slot] = g_wts[e];
}

// ---------------------------------------------------------------------------
// K4: per-cell GEMM.  One CTA of 128 threads per cell, batches of 32 slots.
//     Tile: 4 slots x 4 cols per thread (8 slot-groups x 16 col-groups).
//     Per warp per c-step: 256B K (2 wf) + 32B y (1 wf).  Packed FFMA2 math.
//     Warps whose 8 slots are all padding skip the loop entirely.
//     contrib[e][f] = w_e * (x_e @ K + b)     (written once; deterministic)
// ---------------------------------------------------------------------------
#define BATCH   32
#define YSTRIDE 36   // 32 slots + 4 pad; keeps float4 16B-aligned

__global__ __launch_bounds__(128) void k_cell_gemm(
    const float* __restrict__ xs,
    const float* __restrict__ kernels,
    const float* __restrict__ biases) {

    int cell = blockIdx.x;
    int start = (int)g_offsets[cell];
    int nent  = (int)g_offsets[cell + 1] - start;
    if (nent == 0) return;

    __shared__ __align__(16) float ksm[C_IN * C_OUT];    // 16KB
    __shared__ __align__(16) float ysm[C_IN * YSTRIDE];  // 9.2KB
    __shared__ float    bsm[C_OUT];
    __shared__ float    wsm[BATCH];
    __shared__ unsigned esm[BATCH];

    int t = threadIdx.x;                 // 128 threads
    int fj = t & 15;                     // 16 column groups of 4 -> 64 cols
    int ei = t >> 4;                     // 8 slot groups of 4 -> 32 slots
    const int yb = ei * 4;               // first of this thread's 4 slots
    const int kb = fj * 4;               // first of this thread's 4 columns

    // stage K (coalesced float4, 8 per thread) and bias
    const float* kg = kernels + (size_t)cell * (C_IN * C_OUT);
    #pragma unroll
    for (int i = t; i < (C_IN * C_OUT) / 4; i += 128)
        ((float4*)ksm)[i] = ((const float4*)kg)[i];
    if (t < C_OUT) bsm[t] = biases[(size_t)cell * C_OUT + t];

    for (int base = 0; base < nent; base += BATCH) {
        int nb = min(BATCH, nent - base);

        __syncthreads();   // prior batch done reading ysm/esm; K staged (1st iter)
        if (t < BATCH) {
            unsigned e = 0xFFFFFFFFu;
            float w = 0.f;
            if (t < nb) {                       // coalesced loads
                e = g_sorted[start + base + t];
                w = g_swts[start + base + t];
            }
            esm[t] = e;
            wsm[t] = w;
        }
        __syncthreads();

        // stage y[c][slot] = w * x[pt][c]  (coalesced xs reads over c)
        #pragma unroll
        for (int i = t; i < BATCH * C_IN; i += 128) {
            int c = i & 63, s = i >> 6;
            unsigned e = esm[s];
            float v = 0.f;
            if (e != 0xFFFFFFFFu) v = wsm[s] * xs[(size_t)(e >> 3) * C_IN + c];
            ysm[c * YSTRIDE + s] = v;
        }
        __syncthreads();

        // warp w owns slots [8w, 8w+8); all-padding warps skip entirely.
        if (yb < nb) {
            unsigned long long a[4][2] = {{0,0},{0,0},{0,0},{0,0}};
            #pragma unroll 8
            for (int c = 0; c < C_IN; c++) {
                float4 y4 = *(const float4*)&ysm[c * YSTRIDE + yb];
                ulonglong2 kk = *(const ulonglong2*)&ksm[c * C_OUT + kb];
                unsigned long long y0 = bcast2(y4.x);
                unsigned long long y1 = bcast2(y4.y);
                unsigned long long y2 = bcast2(y4.z);
                unsigned long long y3 = bcast2(y4.w);
                ffma2(a[0][0], y0, kk.x); ffma2(a[0][1], y0, kk.y);
                ffma2(a[1][0], y1, kk.x); ffma2(a[1][1], y1, kk.y);
                ffma2(a[2][0], y2, kk.x); ffma2(a[2][1], y2, kk.y);
                ffma2(a[3][0], y3, kk.x); ffma2(a[3][1], y3, kk.y);
            }

            #pragma unroll
            for (int j = 0; j < 4; j++) {
                int slot = yb + j;
                if (slot < nb) {
                    unsigned e = esm[slot];
                    float w = wsm[slot];
                    float2 lo = unpack2(a[j][0]);
                    float2 hi = unpack2(a[j][1]);
                    float4 o;
                    o.x = lo.x + w * bsm[kb + 0];
                    o.y = lo.y + w * bsm[kb + 1];
                    o.z = hi.x + w * bsm[kb + 2];
                    o.w = hi.y + w * bsm[kb + 3];
                    *(float4*)&g_contrib[(size_t)e * C_OUT + kb] = o;
                }
            }
        }
    }
}

// ---------------------------------------------------------------------------
// K5: deterministic reduction of the 8 corner contributions per point.
//     float4 per thread: 8 independent LDG.128 (MLP=8) + 1 STG.128.
// ---------------------------------------------------------------------------
__global__ void k_reduce(float* __restrict__ out) {
    int i = blockIdx.x * blockDim.x + threadIdx.x;   // over NPTS*16 float4s
    if (i >= NPTS * (C_OUT / 4)) return;
    int n = i >> 4, q = i & 15;

    const float4* cp = (const float4*)g_contrib;
    size_t base = (size_t)n * 8 * (C_OUT / 4) + q;

    float4 v0 = cp[base + 0 * (C_OUT / 4)];
    float4 v1 = cp[base + 1 * (C_OUT / 4)];
    float4 v2 = cp[base + 2 * (C_OUT / 4)];
    float4 v3 = cp[base + 3 * (C_OUT / 4)];
    float4 v4 = cp[base + 4 * (C_OUT / 4)];
    float4 v5 = cp[base + 5 * (C_OUT / 4)];
    float4 v6 = cp[base + 6 * (C_OUT / 4)];
    float4 v7 = cp[base + 7 * (C_OUT / 4)];

    float4 s;
    s.x = ((v0.x + v1.x) + (v2.x + v3.x)) + ((v4.x + v5.x) + (v6.x + v7.x));
    s.y = ((v0.y + v1.y) + (v2.y + v3.y)) + ((v4.y + v5.y) + (v6.y + v7.y));
    s.z = ((v0.z + v1.z) + (v2.z + v3.z)) + ((v4.z + v5.z) + (v6.z + v7.z));
    s.w = ((v0.w + v1.w) + (v2.w + v3.w)) + ((v4.w + v5.w) + (v6.w + v7.w));

    ((float4*)out)[i] = s;
}

// ---------------------------------------------------------------------------
// Launcher (graph-capturable: kernels only, default stream).  5 launches;
// k_cell_gemm sits in the slot the fixed ncu capture lands on.
// ---------------------------------------------------------------------------
extern "C" void kernel_launch(void* const* d_in, const int* in_sizes, int n_in,
                              void* d_out, int out_size) {
    const int*   pidx    = (const int*)  d_in[0];  // (N,1) int32
    const float* pos     = (const float*)d_in[1];  // (N,3)
    const float* xs      = (const float*)d_in[2];  // (N,64)
    const float* kernels = (const float*)d_in[3];  // (4,16,16,16,64,64)
    const float* biases  = (const float*)d_in[4];  // (4,16,16,16,64)
    float* out = (float*)d_out;                    // (N,64)
    (void)in_sizes; (void)n_in; (void)out_size;

    k_prep<<<(NPTS + 255) / 256, 256>>>(pidx, pos);
    k_scan<<<1, 512>>>();
    k_scatter<<<(NENT + 255) / 256, 256>>>();
    k_cell_gemm<<<NCELLS, 128>>>(xs, kernels, biases);
    k_reduce<<<(NPTS * (C_OUT / 4) + 255) / 256, 256>>>(out);
}

// round 8
// speedup vs baseline: 1.0140x; 1.0140x over previous
#include <cuda_runtime.h>
#include <stdint.h>

// Problem constants (fixed by the dataset)
#define NPTS      32768
#define NKERN     4
#define GRID      16
#define C_IN      64
#define C_OUT     64
#define NCELLS    (NKERN * GRID * GRID * GRID)   // 16384
#define NENT      (NPTS * 8)                     // 262144
#define CPC       8                              // cells per CTA (pipeline depth)
#define NGEMM     (NCELLS / CPC)                 // 2048 CTAs

// ---------------------------------------------------------------------------
// Device scratch (static __device__ globals; no cudaMalloc anywhere).
// g_counts: zero-initialized at load; re-zeroed in k_scatter for the next call.
// ---------------------------------------------------------------------------
__device__ unsigned g_counts[NCELLS];
__device__ unsigned g_offsets[NCELLS + 1];
__device__ unsigned g_cursor[NCELLS];
__device__ unsigned g_cells[NENT];     // cell id per (point,corner) entry
__device__ float    g_wts[NENT];       // trilinear weight per entry
__device__ unsigned g_sorted[NENT];    // entry ids grouped by cell
__device__ float    g_swts[NENT];      // weights in sorted order (coalesced read)
__device__ float    g_contrib[(size_t)NENT * C_OUT];  // 67MB staging (deterministic)

// packed f32x2 FMA: d = a*b + d  (SASS FFMA2 — 2 fp32 MACs per lane per issue)
__device__ __forceinline__ void ffma2(unsigned long long& d,
                                      unsigned long long a,
                                      unsigned long long b) {
    asm("fma.rn.f32x2 %0, %1, %2, %0;" : "+l"(d) : "l"(a), "l"(b));
}
__device__ __forceinline__ unsigned long long bcast2(float v) {
    unsigned long long r;
    asm("mov.b64 %0, {%1, %1};" : "=l"(r) : "f"(v));
    return r;
}
__device__ __forceinline__ float2 unpack2(unsigned long long v) {
    float2 r;
    asm("mov.b64 {%0, %1}, %2;" : "=f"(r.x), "=f"(r.y) : "l"(v));
    return r;
}
__device__ __forceinline__ uint32_t smem_u32(const void* p) {
    uint32_t a;
    asm("{ .reg .u64 t; cvta.to.shared.u64 t, %1; cvt.u32.u64 %0, t; }"
        : "=r"(a) : "l"(p));
    return a;
}
__device__ __forceinline__ void mbar_init(uint32_t mbar, unsigned count) {
    asm volatile("mbarrier.init.shared.b64 [%0], %1;" :: "r"(mbar), "r"(count) : "memory");
}
__device__ __forceinline__ void mbar_expect_tx(uint32_t mbar, unsigned bytes) {
    asm volatile("mbarrier.arrive.expect_tx.shared.b64 _, [%0], %1;"
                 :: "r"(mbar), "r"(bytes) : "memory");
}
__device__ __forceinline__ void mbar_wait(uint32_t mbar, unsigned parity) {
    asm volatile(
        "{\n\t.reg .pred P;\n"
        "W%=:\n\t"
        "mbarrier.try_wait.parity.shared::cta.b64 P, [%0], %1, 0x989680;\n\t"
        "@P bra D%=;\n\t"
        "bra W%=;\n"
        "D%=:\n\t}"
        :: "r"(mbar), "r"(parity) : "memory");
}
__device__ __forceinline__ void bulk_g2s(uint32_t dst, const void* src,
                                         unsigned bytes, uint32_t mbar) {
    asm volatile(
        "cp.async.bulk.shared::cta.global.mbarrier::complete_tx::bytes "
        "[%0], [%1], %2, [%3];"
        :: "r"(dst), "l"(src), "r"(bytes), "r"(mbar) : "memory");
}

// ---------------------------------------------------------------------------
// K1: per-point corner cells + weights, histogram cells
// ---------------------------------------------------------------------------
__global__ void k_prep(const int* __restrict__ pidx,
                       const float* __restrict__ pos) {
    int n = blockIdx.x * blockDim.x + threadIdx.x;
    if (n >= NPTS) return;

    float lx = pos[n * 3 + 0] * (float)GRID - 0.5f;
    float ly = pos[n * 3 + 1] * (float)GRID - 0.5f;
    float lz = pos[n * 3 + 2] * (float)GRID - 0.5f;
    float fx = floorf(lx), fy = floorf(ly), fz = floorf(lz);
    float cwx = lx - fx, cwy = ly - fy, cwz = lz - fz;
    float fwx = 1.f - cwx, fwy = 1.f - cwy, fwz = 1.f - cwz;
    int ix = (int)fx, iy = (int)fy, iz = (int)fz;
    int pi = pidx[n];

    #pragma unroll
    for (int k = 0; k < 8; k++) {
        int bx = k & 1, by = (k >> 1) & 1, bz = (k >> 2) & 1;
        int jx = min(max(ix + bx, 0), GRID - 1);
        int jy = min(max(iy + by, 0), GRID - 1);
        int jz = min(max(iz + bz, 0), GRID - 1);
        float w = (bx ? cwx : fwx) * (by ? cwy : fwy) * (bz ? cwz : fwz);
        unsigned cell = (((unsigned)pi * GRID + jz) * GRID + jy) * GRID + jx;
        g_cells[n * 8 + k] = cell;
        g_wts[n * 8 + k] = w;
        atomicAdd(&g_counts[cell], 1u);
    }
}

// ---------------------------------------------------------------------------
// K2: single-block exclusive scan of 16384 counts
// ---------------------------------------------------------------------------
__global__ void k_scan() {
    __shared__ unsigned part[512];
    int t = threadIdx.x;
    unsigned sum = 0;
    #pragma unroll 4
    for (int i = 0; i < 32; i++) sum += g_counts[t * 32 + i];
    part[t] = sum;
    __syncthreads();
    for (int off = 1; off < 512; off <<= 1) {
        unsigned v = 0;
        if (t >= off) v = part[t - off];
        __syncthreads();
        if (t >= off) part[t] += v;
        __syncthreads();
    }
    unsigned run = (t == 0) ? 0u : part[t - 1];
    #pragma unroll 4
    for (int i = 0; i < 32; i++) {
        int idx = t * 32 + i;
        g_offsets[idx] = run;
        g_cursor[idx] = run;
        run += g_counts[idx];
    }
    if (t == 511) g_offsets[NCELLS] = run;   // == NENT
}

// ---------------------------------------------------------------------------
// K3: scatter entries into cell-grouped order (+ sorted weights, counts reset)
// ---------------------------------------------------------------------------
__global__ void k_scatter() {
    int e = blockIdx.x * blockDim.x + threadIdx.x;
    if (e < NCELLS) g_counts[e] = 0u;            // reset for next call
    if (e >= NENT) return;
    unsigned cell = g_cells[e];
    unsigned slot = atomicAdd(&g_cursor[cell], 1u);
    g_sorted[slot] = (unsigned)e;
    g_swts[slot] = g_wts[e];
}

// ---------------------------------------------------------------------------
// K4: pipelined per-cell GEMM.  One CTA (128 thr) owns CPC=8 consecutive
//     cells.  K tiles (16KB) + bias (256B) double-buffered in SMEM, fetched
//     with cp.async.bulk + mbarrier; cell i+1's copy is issued BEFORE cell
//     i's compute so the K stream overlaps the math.
//     Tile: 4 slots x 4 cols per thread, packed FFMA2.
//     contrib[e][f] = w_e * (x_e @ K + b)     (written once; deterministic)
// ---------------------------------------------------------------------------
#define BATCH   32
#define YSTRIDE 36   // 32 slots + 4 pad; keeps float4 16B-aligned

#define KBYTES   (C_IN * C_OUT * 4)          // 16384
#define BBYTES   (C_OUT * 4)                 // 256
#define TXBYTES  (KBYTES + BBYTES)           // 16640

__global__ __launch_bounds__(128) void k_cell_gemm(
    const float* __restrict__ xs,
    const float* __restrict__ kernels,
    const float* __restrict__ biases) {

    __shared__ __align__(16) float ksm[2][C_IN * C_OUT];   // 32KB
    __shared__ __align__(16) float bsm[2][C_OUT];          // 512B
    __shared__ __align__(16) float ysm[C_IN * YSTRIDE];    // 9.2KB
    __shared__ float    wsm[BATCH];
    __shared__ unsigned esm[BATCH];
    __shared__ __align__(8) unsigned long long mbar_s[2];

    int t = threadIdx.x;                 // 128 threads
    int fj = t & 15;                     // 16 column groups of 4 -> 64 cols
    int ei = t >> 4;                     // 8 slot groups of 4 -> 32 slots
    const int yb = ei * 4;
    const int kb = fj * 4;

    uint32_t mb0 = smem_u32(&mbar_s[0]);
    uint32_t mb1 = smem_u32(&mbar_s[1]);
    uint32_t kd0 = smem_u32(&ksm[0][0]);
    uint32_t kd1 = smem_u32(&ksm[1][0]);
    uint32_t bd0 = smem_u32(&bsm[0][0]);
    uint32_t bd1 = smem_u32(&bsm[1][0]);

    int cell0 = blockIdx.x * CPC;

    if (t == 0) {
        mbar_init(mb0, 1);
        mbar_init(mb1, 1);
    }
    __syncthreads();

    // prologue: issue cell0 into buffer 0
    if (t == 0) {
        mbar_expect_tx(mb0, TXBYTES);
        bulk_g2s(kd0, kernels + (size_t)cell0 * (C_IN * C_OUT), KBYTES, mb0);
        bulk_g2s(bd0, biases  + (size_t)cell0 * C_OUT,          BBYTES, mb0);
    }

    unsigned parity[2] = {0u, 0u};

    for (int ci = 0; ci < CPC; ci++) {
        int cell = cell0 + ci;
        int buf  = ci & 1;

        // issue next cell's K into the other buffer (freed by the
        // __syncthreads at the end of cell ci-1's compute)
        if (ci + 1 < CPC && t == 0) {
            int nbuf = buf ^ 1;
            uint32_t mb = nbuf ? mb1 : mb0;
            uint32_t kd = nbuf ? kd1 : kd0;
            uint32_t bd = nbuf ? bd1 : bd0;
            mbar_expect_tx(mb, TXBYTES);
            bulk_g2s(kd, kernels + (size_t)(cell + 1) * (C_IN * C_OUT), KBYTES, mb);
            bulk_g2s(bd, biases  + (size_t)(cell + 1) * C_OUT,          BBYTES, mb);
        }

        // wait for this cell's K
        mbar_wait(buf ? mb1 : mb0, parity[buf]);
        parity[buf] ^= 1u;

        int start = (int)g_offsets[cell];
        int nent  = (int)g_offsets[cell + 1] - start;

        const float* kcur = ksm[buf];
        const float* bcur = bsm[buf];

        for (int base = 0; base < nent; base += BATCH) {
            int nb = min(BATCH, nent - base);

            __syncthreads();   // prior batch done reading ysm/esm
            if (t < BATCH) {
                unsigned e = 0xFFFFFFFFu;
                float w = 0.f;
                if (t < nb) {
                    e = g_sorted[start + base + t];
                    w = g_swts[start + base + t];
                }
                esm[t] = e;
                wsm[t] = w;
            }
            __syncthreads();

            // stage y[c][slot] = w * x[pt][c]
            #pragma unroll
            for (int i = t; i < BATCH * C_IN; i += 128) {
                int c = i & 63, s = i >> 6;
                unsigned e = esm[s];
                float v = 0.f;
                if (e != 0xFFFFFFFFu) v = wsm[s] * xs[(size_t)(e >> 3) * C_IN + c];
                ysm[c * YSTRIDE + s] = v;
            }
            __syncthreads();

            // warp w owns slots [8w, 8w+8); all-padding warps skip.
            if (yb < nb) {
                unsigned long long a[4][2] = {{0,0},{0,0},{0,0},{0,0}};
                #pragma unroll 8
                for (int c = 0; c < C_IN; c++) {
                    float4 y4 = *(const float4*)&ysm[c * YSTRIDE + yb];
                    ulonglong2 kk = *(const ulonglong2*)&kcur[c * C_OUT + kb];
                    unsigned long long y0 = bcast2(y4.x);
                    unsigned long long y1 = bcast2(y4.y);
                    unsigned long long y2 = bcast2(y4.z);
                    unsigned long long y3 = bcast2(y4.w);
                    ffma2(a[0][0], y0, kk.x); ffma2(a[0][1], y0, kk.y);
                    ffma2(a[1][0], y1, kk.x); ffma2(a[1][1], y1, kk.y);
                    ffma2(a[2][0], y2, kk.x); ffma2(a[2][1], y2, kk.y);
                    ffma2(a[3][0], y3, kk.x); ffma2(a[3][1], y3, kk.y);
                }

                #pragma unroll
                for (int j = 0; j < 4; j++) {
                    int slot = yb + j;
                    if (slot < nb) {
                        unsigned e = esm[slot];
                        float w = wsm[slot];
                        float2 lo = unpack2(a[j][0]);
                        float2 hi = unpack2(a[j][1]);
                        float4 o;
                        o.x = lo.x + w * bcur[kb + 0];
                        o.y = lo.y + w * bcur[kb + 1];
                        o.z = hi.x + w * bcur[kb + 2];
                        o.w = hi.y + w * bcur[kb + 3];
                        *(float4*)&g_contrib[(size_t)e * C_OUT + kb] = o;
                    }
                }
            }
        }

        __syncthreads();   // all reads of ksm[buf]/bsm[buf] done before refill
    }
}

// ---------------------------------------------------------------------------
// K5: deterministic reduction of the 8 corner contributions per point.
// ---------------------------------------------------------------------------
__global__ void k_reduce(float* __restrict__ out) {
    int i = blockIdx.x * blockDim.x + threadIdx.x;   // over NPTS*16 float4s
    if (i >= NPTS * (C_OUT / 4)) return;
    int n = i >> 4, q = i & 15;

    const float4* cp = (const float4*)g_contrib;
    size_t base = (size_t)n * 8 * (C_OUT / 4) + q;

    float4 v0 = cp[base + 0 * (C_OUT / 4)];
    float4 v1 = cp[base + 1 * (C_OUT / 4)];
    float4 v2 = cp[base + 2 * (C_OUT / 4)];
    float4 v3 = cp[base + 3 * (C_OUT / 4)];
    float4 v4 = cp[base + 4 * (C_OUT / 4)];
    float4 v5 = cp[base + 5 * (C_OUT / 4)];
    float4 v6 = cp[base + 6 * (C_OUT / 4)];
    float4 v7 = cp[base + 7 * (C_OUT / 4)];

    float4 s;
    s.x = ((v0.x + v1.x) + (v2.x + v3.x)) + ((v4.x + v5.x) + (v6.x + v7.x));
    s.y = ((v0.y + v1.y) + (v2.y + v3.y)) + ((v4.y + v5.y) + (v6.y + v7.y));
    s.z = ((v0.z + v1.z) + (v2.z + v3.z)) + ((v4.z + v5.z) + (v6.z + v7.z));
    s.w = ((v0.w + v1.w) + (v2.w + v3.w)) + ((v4.w + v5.w) + (v6.w + v7.w));

    ((float4*)out)[i] = s;
}

// ---------------------------------------------------------------------------
// Launcher (graph-capturable).  k_cell_gemm stays the 4th launch so the
// fixed ncu capture lands on it again.
// ---------------------------------------------------------------------------
extern "C" void kernel_launch(void* const* d_in, const int* in_sizes, int n_in,
                              void* d_out, int out_size) {
    const int*   pidx    = (const int*)  d_in[0];  // (N,1) int32
    const float* pos     = (const float*)d_in[1];  // (N,3)
    const float* xs      = (const float*)d_in[2];  // (N,64)
    const float* kernels = (const float*)d_in[3];  // (4,16,16,16,64,64)
    const float* biases  = (const float*)d_in[4];  // (4,16,16,16,64)
    float* out = (float*)d_out;                    // (N,64)
    (void)in_sizes; (void)n_in; (void)out_size;

    k_prep<<<(NPTS + 255) / 256, 256>>>(pidx, pos);
    k_scan<<<1, 512>>>();
    k_scatter<<<(NENT + 255) / 256, 256>>>();
    k_cell_gemm<<<NGEMM, 128>>>(xs, kernels, biases);
    k_reduce<<<(NPTS * (C_OUT / 4) + 255) / 256, 256>>>(out);
}

// round 9
// speedup vs baseline: 1.1045x; 1.0893x over previous
#include <cuda_runtime.h>
#include <stdint.h>

// Problem constants (fixed by the dataset)
#define NPTS      32768
#define NKERN     4
#define GRID      16
#define C_IN      64
#define C_OUT     64
#define NCELLS    (NKERN * GRID * GRID * GRID)   // 16384
#define NENT      (NPTS * 8)                     // 262144
#define CPC       8                              // cells per CTA (pipeline depth)
#define NGEMM     (NCELLS / CPC)                 // 2048 CTAs

// ---------------------------------------------------------------------------
// Device scratch (static __device__ globals; no cudaMalloc anywhere).
// g_counts: zero-initialized at load; re-zeroed in k_scatter for the next call.
// ---------------------------------------------------------------------------
__device__ unsigned g_counts[NCELLS];
__device__ unsigned g_offsets[NCELLS + 1];
__device__ unsigned g_cursor[NCELLS];
__device__ unsigned g_cells[NENT];     // cell id per (point,corner) entry
__device__ float    g_wts[NENT];       // trilinear weight per entry
__device__ unsigned g_sorted[NENT];    // entry ids grouped by cell
__device__ float    g_swts[NENT];      // weights in sorted order (coalesced read)

// packed f32x2 FMA: d = a*b + d  (SASS FFMA2 — 2 fp32 MACs per lane per issue)
__device__ __forceinline__ void ffma2(unsigned long long& d,
                                      unsigned long long a,
                                      unsigned long long b) {
    asm("fma.rn.f32x2 %0, %1, %2, %0;" : "+l"(d) : "l"(a), "l"(b));
}
__device__ __forceinline__ unsigned long long bcast2(float v) {
    unsigned long long r;
    asm("mov.b64 %0, {%1, %1};" : "=l"(r) : "f"(v));
    return r;
}
__device__ __forceinline__ float2 unpack2(unsigned long long v) {
    float2 r;
    asm("mov.b64 {%0, %1}, %2;" : "=f"(r.x), "=f"(r.y) : "l"(v));
    return r;
}
__device__ __forceinline__ uint32_t smem_u32(const void* p) {
    uint32_t a;
    asm("{ .reg .u64 t; cvta.to.shared.u64 t, %1; cvt.u32.u64 %0, t; }"
        : "=r"(a) : "l"(p));
    return a;
}
__device__ __forceinline__ void mbar_init(uint32_t mbar, unsigned count) {
    asm volatile("mbarrier.init.shared.b64 [%0], %1;" :: "r"(mbar), "r"(count) : "memory");
}
__device__ __forceinline__ void mbar_expect_tx(uint32_t mbar, unsigned bytes) {
    asm volatile("mbarrier.arrive.expect_tx.shared.b64 _, [%0], %1;"
                 :: "r"(mbar), "r"(bytes) : "memory");
}
__device__ __forceinline__ void mbar_wait(uint32_t mbar, unsigned parity) {
    asm volatile(
        "{\n\t.reg .pred P;\n"
        "W%=:\n\t"
        "mbarrier.try_wait.parity.shared::cta.b64 P, [%0], %1, 0x989680;\n\t"
        "@P bra D%=;\n\t"
        "bra W%=;\n"
        "D%=:\n\t}"
        :: "r"(mbar), "r"(parity) : "memory");
}
__device__ __forceinline__ void bulk_g2s(uint32_t dst, const void* src,
                                         unsigned bytes, uint32_t mbar) {
    asm volatile(
        "cp.async.bulk.shared::cta.global.mbarrier::complete_tx::bytes "
        "[%0], [%1], %2, [%3];"
        :: "r"(dst), "l"(src), "r"(bytes), "r"(mbar) : "memory");
}
// vectorized fp32 global reduction (sm_90+): one 16B atomic add, no return
__device__ __forceinline__ void red_add_v4(float* gptr, float4 v) {
    asm volatile("red.global.add.v4.f32 [%0], {%1, %2, %3, %4};"
                 :: "l"(gptr), "f"(v.x), "f"(v.y), "f"(v.z), "f"(v.w)
                 : "memory");
}

// ---------------------------------------------------------------------------
// K1: zero the output (grid-stride float4) + per-point corners/weights +
//     cell histogram
// ---------------------------------------------------------------------------
__global__ void k_prep(const int* __restrict__ pidx,
                       const float* __restrict__ pos,
                       float* __restrict__ out) {
    int n = blockIdx.x * blockDim.x + threadIdx.x;

    // zero d_out: NPTS*16 float4s over NPTS threads -> 16 coalesced stores
    float4 z = make_float4(0.f, 0.f, 0.f, 0.f);
    #pragma unroll
    for (int i = n; i < NPTS * (C_OUT / 4); i += NPTS)
        ((float4*)out)[i] = z;

    if (n >= NPTS) return;

    float lx = pos[n * 3 + 0] * (float)GRID - 0.5f;
    float ly = pos[n * 3 + 1] * (float)GRID - 0.5f;
    float lz = pos[n * 3 + 2] * (float)GRID - 0.5f;
    float fx = floorf(lx), fy = floorf(ly), fz = floorf(lz);
    float cwx = lx - fx, cwy = ly - fy, cwz = lz - fz;
    float fwx = 1.f - cwx, fwy = 1.f - cwy, fwz = 1.f - cwz;
    int ix = (int)fx, iy = (int)fy, iz = (int)fz;
    int pi = pidx[n];

    #pragma unroll
    for (int k = 0; k < 8; k++) {
        int bx = k & 1, by = (k >> 1) & 1, bz = (k >> 2) & 1;
        int jx = min(max(ix + bx, 0), GRID - 1);
        int jy = min(max(iy + by, 0), GRID - 1);
        int jz = min(max(iz + bz, 0), GRID - 1);
        float w = (bx ? cwx : fwx) * (by ? cwy : fwy) * (bz ? cwz : fwz);
        unsigned cell = (((unsigned)pi * GRID + jz) * GRID + jy) * GRID + jx;
        g_cells[n * 8 + k] = cell;
        g_wts[n * 8 + k] = w;
        atomicAdd(&g_counts[cell], 1u);
    }
}

// ---------------------------------------------------------------------------
// K2: single-block exclusive scan of 16384 counts
// ---------------------------------------------------------------------------
__global__ void k_scan() {
    __shared__ unsigned part[512];
    int t = threadIdx.x;
    unsigned sum = 0;
    #pragma unroll 4
    for (int i = 0; i < 32; i++) sum += g_counts[t * 32 + i];
    part[t] = sum;
    __syncthreads();
    for (int off = 1; off < 512; off <<= 1) {
        unsigned v = 0;
        if (t >= off) v = part[t - off];
        __syncthreads();
        if (t >= off) part[t] += v;
        __syncthreads();
    }
    unsigned run = (t == 0) ? 0u : part[t - 1];
    #pragma unroll 4
    for (int i = 0; i < 32; i++) {
        int idx = t * 32 + i;
        g_offsets[idx] = run;
        g_cursor[idx] = run;
        run += g_counts[idx];
    }
    if (t == 511) g_offsets[NCELLS] = run;   // == NENT
}

// ---------------------------------------------------------------------------
// K3: scatter entries into cell-grouped order (+ sorted weights, counts reset)
// ---------------------------------------------------------------------------
__global__ void k_scatter() {
    int e = blockIdx.x * blockDim.x + threadIdx.x;
    if (e < NCELLS) g_counts[e] = 0u;            // reset for next call
    if (e >= NENT) return;
    unsigned cell = g_cells[e];
    unsigned slot = atomicAdd(&g_cursor[cell], 1u);
    g_sorted[slot] = (unsigned)e;
    g_swts[slot] = g_wts[e];
}

// ---------------------------------------------------------------------------
// K4: pipelined per-cell GEMM, epilogue accumulates straight into d_out with
//     red.global.add.v4.f32 (no staging buffer, no reduce kernel).
//     One CTA (128 thr) owns CPC=8 consecutive cells; K (16KB)+bias double-
//     buffered via cp.async.bulk + mbarrier.  4 slots x 4 cols per thread,
//     packed FFMA2 inner loop.  Warps with only padding slots skip compute.
// ---------------------------------------------------------------------------
#define BATCH   32
#define YSTRIDE 36   // 32 slots + 4 pad; keeps float4 16B-aligned

#define KBYTES   (C_IN * C_OUT * 4)          // 16384
#define BBYTES   (C_OUT * 4)                 // 256
#define TXBYTES  (KBYTES + BBYTES)           // 16640

__global__ __launch_bounds__(128) void k_cell_gemm(
    const float* __restrict__ xs,
    const float* __restrict__ kernels,
    const float* __restrict__ biases,
    float* __restrict__ out) {

    __shared__ __align__(16) float ksm[2][C_IN * C_OUT];   // 32KB
    __shared__ __align__(16) float bsm[2][C_OUT];          // 512B
    __shared__ __align__(16) float ysm[C_IN * YSTRIDE];    // 9.2KB
    __shared__ float    wsm[BATCH];
    __shared__ unsigned esm[BATCH];
    __shared__ __align__(8) unsigned long long mbar_s[2];

    int t = threadIdx.x;                 // 128 threads
    int fj = t & 15;                     // 16 column groups of 4 -> 64 cols
    int ei = t >> 4;                     // 8 slot groups of 4 -> 32 slots
    const int yb = ei * 4;
    const int kb = fj * 4;

    uint32_t mb0 = smem_u32(&mbar_s[0]);
    uint32_t mb1 = smem_u32(&mbar_s[1]);
    uint32_t kd0 = smem_u32(&ksm[0][0]);
    uint32_t kd1 = smem_u32(&ksm[1][0]);
    uint32_t bd0 = smem_u32(&bsm[0][0]);
    uint32_t bd1 = smem_u32(&bsm[1][0]);

    int cell0 = blockIdx.x * CPC;

    if (t == 0) {
        mbar_init(mb0, 1);
        mbar_init(mb1, 1);
    }
    __syncthreads();

    // prologue: issue cell0 into buffer 0
    if (t == 0) {
        mbar_expect_tx(mb0, TXBYTES);
        bulk_g2s(kd0, kernels + (size_t)cell0 * (C_IN * C_OUT), KBYTES, mb0);
        bulk_g2s(bd0, biases  + (size_t)cell0 * C_OUT,          BBYTES, mb0);
    }

    unsigned parity[2] = {0u, 0u};

    for (int ci = 0; ci < CPC; ci++) {
        int cell = cell0 + ci;
        int buf  = ci & 1;

        // issue next cell's K into the other buffer
        if (ci + 1 < CPC && t == 0) {
            int nbuf = buf ^ 1;
            uint32_t mb = nbuf ? mb1 : mb0;
            uint32_t kd = nbuf ? kd1 : kd0;
            uint32_t bd = nbuf ? bd1 : bd0;
            mbar_expect_tx(mb, TXBYTES);
            bulk_g2s(kd, kernels + (size_t)(cell + 1) * (C_IN * C_OUT), KBYTES, mb);
            bulk_g2s(bd, biases  + (size_t)(cell + 1) * C_OUT,          BBYTES, mb);
        }

        // wait for this cell's K
        mbar_wait(buf ? mb1 : mb0, parity[buf]);
        parity[buf] ^= 1u;

        int start = (int)g_offsets[cell];
        int nent  = (int)g_offsets[cell + 1] - start;

        const float* kcur = ksm[buf];
        const float* bcur = bsm[buf];

        for (int base = 0; base < nent; base += BATCH) {
            int nb = min(BATCH, nent - base);

            __syncthreads();   // prior batch done reading ysm/esm
            if (t < BATCH) {
                unsigned e = 0xFFFFFFFFu;
                float w = 0.f;
                if (t < nb) {
                    e = g_sorted[start + base + t];
                    w = g_swts[start + base + t];
                }
                esm[t] = e;
                wsm[t] = w;
            }
            __syncthreads();

            // stage y[c][slot] = w * x[pt][c]
            #pragma unroll
            for (int i = t; i < BATCH * C_IN; i += 128) {
                int c = i & 63, s = i >> 6;
                unsigned e = esm[s];
                float v = 0.f;
                if (e != 0xFFFFFFFFu) v = wsm[s] * xs[(size_t)(e >> 3) * C_IN + c];
                ysm[c * YSTRIDE + s] = v;
            }
            __syncthreads();

            // warp w owns slots [8w, 8w+8); all-padding warps skip.
            if (yb < nb) {
                unsigned long long a[4][2] = {{0,0},{0,0},{0,0},{0,0}};
                #pragma unroll 8
                for (int c = 0; c < C_IN; c++) {
                    float4 y4 = *(const float4*)&ysm[c * YSTRIDE + yb];
                    ulonglong2 kk = *(const ulonglong2*)&kcur[c * C_OUT + kb];
                    unsigned long long y0 = bcast2(y4.x);
                    unsigned long long y1 = bcast2(y4.y);
                    unsigned long long y2 = bcast2(y4.z);
                    unsigned long long y3 = bcast2(y4.w);
                    ffma2(a[0][0], y0, kk.x); ffma2(a[0][1], y0, kk.y);
                    ffma2(a[1][0], y1, kk.x); ffma2(a[1][1], y1, kk.y);
                    ffma2(a[2][0], y2, kk.x); ffma2(a[2][1], y2, kk.y);
                    ffma2(a[3][0], y3, kk.x); ffma2(a[3][1], y3, kk.y);
                }

                #pragma unroll
                for (int j = 0; j < 4; j++) {
                    int slot = yb + j;
                    if (slot < nb) {
                        unsigned e = esm[slot];
                        float w = wsm[slot];
                        float2 lo = unpack2(a[j][0]);
                        float2 hi = unpack2(a[j][1]);
                        float4 o;
                        o.x = lo.x + w * bcur[kb + 0];
                        o.y = lo.y + w * bcur[kb + 1];
                        o.z = hi.x + w * bcur[kb + 2];
                        o.w = hi.y + w * bcur[kb + 3];
                        // accumulate straight into the output row of point e>>3
                        red_add_v4(&out[(size_t)(e >> 3) * C_OUT + kb], o);
                    }
                }
            }
        }

        __syncthreads();   // all reads of ksm[buf]/bsm[buf] done before refill
    }
}

// ---------------------------------------------------------------------------
// Launcher (graph-capturable).  4 launches; k_cell_gemm stays 4th so the
// fixed ncu capture keeps landing on it.
// ---------------------------------------------------------------------------
extern "C" void kernel_launch(void* const* d_in, const int* in_sizes, int n_in,
                              void* d_out, int out_size) {
    const int*   pidx    = (const int*)  d_in[0];  // (N,1) int32
    const float* pos     = (const float*)d_in[1];  // (N,3)
    const float* xs      = (const float*)d_in[2];  // (N,64)
    const float* kernels = (const float*)d_in[3];  // (4,16,16,16,64,64)
    const float* biases  = (const float*)d_in[4];  // (4,16,16,16,64)
    float* out = (float*)d_out;                    // (N,64)
    (void)in_sizes; (void)n_in; (void)out_size;

    k_prep<<<(NPTS + 255) / 256, 256>>>(pidx, pos, out);
    k_scan<<<1, 512>>>();
    k_scatter<<<(NENT + 255) / 256, 256>>>();
    k_cell_gemm<<<NGEMM, 128>>>(xs, kernels, biases, out);
}

// round 10
// speedup vs baseline: 1.2736x; 1.1531x over previous
#include <cuda_runtime.h>
#include <stdint.h>

// Problem constants (fixed by the dataset)
#define NPTS      32768
#define NKERN     4
#define GRID      16
#define C_IN      64
#define C_OUT     64
#define NCELLS    (NKERN * GRID * GRID * GRID)   // 16384
#define NENT      (NPTS * 8)                     // 262144
#define CPC       8                              // cells per CTA
#define NGEMM     (NCELLS / CPC)                 // 2048 CTAs
#define B         16                             // batch (slots)
#define YROW      68                             // floats per y row (272B, 16B-aligned)

// ---------------------------------------------------------------------------
// Device scratch (static __device__ globals; no cudaMalloc anywhere).
// g_counts zero at load; re-zeroed in k_scatter.  g_sorted/g_swts padded +B
// (pad stays zero forever -> e=0 is a safe in-bounds dummy row).
// ---------------------------------------------------------------------------
__device__ unsigned g_counts[NCELLS];
__device__ unsigned g_offsets[NCELLS + 1];
__device__ unsigned g_cursor[NCELLS];
__device__ unsigned g_cells[NENT];
__device__ float    g_wts[NENT];
__device__ unsigned g_sorted[NENT + B];
__device__ float    g_swts[NENT + B];

// ---------------------------------------------------------------------------
// asm helpers
// ---------------------------------------------------------------------------
__device__ __forceinline__ void ffma2(unsigned long long& d,
                                      unsigned long long a,
                                      unsigned long long b) {
    asm("fma.rn.f32x2 %0, %1, %2, %0;" : "+l"(d) : "l"(a), "l"(b));
}
__device__ __forceinline__ unsigned long long bcast2(float v) {
    unsigned long long r;
    asm("mov.b64 %0, {%1, %1};" : "=l"(r) : "f"(v));
    return r;
}
__device__ __forceinline__ float2 unpack2(unsigned long long v) {
    float2 r;
    asm("mov.b64 {%0, %1}, %2;" : "=f"(r.x), "=f"(r.y) : "l"(v));
    return r;
}
__device__ __forceinline__ uint32_t smem_u32(const void* p) {
    uint32_t a;
    asm("{ .reg .u64 t; cvta.to.shared.u64 t, %1; cvt.u32.u64 %0, t; }"
        : "=r"(a) : "l"(p));
    return a;
}
__device__ __forceinline__ void mbar_init(uint32_t mbar, unsigned count) {
    asm volatile("mbarrier.init.shared.b64 [%0], %1;" :: "r"(mbar), "r"(count) : "memory");
}
__device__ __forceinline__ void mbar_expect_tx(uint32_t mbar, unsigned bytes) {
    asm volatile("mbarrier.arrive.expect_tx.shared.b64 _, [%0], %1;"
                 :: "r"(mbar), "r"(bytes) : "memory");
}
__device__ __forceinline__ void mbar_wait(uint32_t mbar, unsigned parity) {
    asm volatile(
        "{\n\t.reg .pred P;\n"
        "W%=:\n\t"
        "mbarrier.try_wait.parity.shared::cta.b64 P, [%0], %1, 0x989680;\n\t"
        "@P bra D%=;\n\t"
        "bra W%=;\n"
        "D%=:\n\t}"
        :: "r"(mbar), "r"(parity) : "memory");
}
__device__ __forceinline__ void bulk_g2s(uint32_t dst, const void* src,
                                         unsigned bytes, uint32_t mbar) {
    asm volatile(
        "cp.async.bulk.shared::cta.global.mbarrier::complete_tx::bytes "
        "[%0], [%1], %2, [%3];"
        :: "r"(dst), "l"(src), "r"(bytes), "r"(mbar) : "memory");
}
__device__ __forceinline__ void red_add_v4(float* gptr, float4 v) {
    asm volatile("red.global.add.v4.f32 [%0], {%1, %2, %3, %4};"
                 :: "l"(gptr), "f"(v.x), "f"(v.y), "f"(v.z), "f"(v.w)
                 : "memory");
}
__device__ __forceinline__ void cp_async16(uint32_t dst, const void* src) {
    asm volatile("cp.async.cg.shared.global [%0], [%1], 16;"
                 :: "r"(dst), "l"(src) : "memory");
}
__device__ __forceinline__ void cp_async4(uint32_t dst, const void* src) {
    asm volatile("cp.async.ca.shared.global [%0], [%1], 4;"
                 :: "r"(dst), "l"(src) : "memory");
}
__device__ __forceinline__ void cp_commit() {
    asm volatile("cp.async.commit_group;" ::: "memory");
}
__device__ __forceinline__ void cp_wait1() {
    asm volatile("cp.async.wait_group 1;" ::: "memory");
}

// ---------------------------------------------------------------------------
// K1: zero d_out + per-point corners/weights + cell histogram
// ---------------------------------------------------------------------------
__global__ void k_prep(const int* __restrict__ pidx,
                       const float* __restrict__ pos,
                       float* __restrict__ out) {
    int n = blockIdx.x * blockDim.x + threadIdx.x;

    float4 z = make_float4(0.f, 0.f, 0.f, 0.f);
    #pragma unroll
    for (int i = n; i < NPTS * (C_OUT / 4); i += NPTS)
        ((float4*)out)[i] = z;

    if (n >= NPTS) return;

    float lx = pos[n * 3 + 0] * (float)GRID - 0.5f;
    float ly = pos[n * 3 + 1] * (float)GRID - 0.5f;
    float lz = pos[n * 3 + 2] * (float)GRID - 0.5f;
    float fx = floorf(lx), fy = floorf(ly), fz = floorf(lz);
    float cwx = lx - fx, cwy = ly - fy, cwz = lz - fz;
    float fwx = 1.f - cwx, fwy = 1.f - cwy, fwz = 1.f - cwz;
    int ix = (int)fx, iy = (int)fy, iz = (int)fz;
    int pi = pidx[n];

    #pragma unroll
    for (int k = 0; k < 8; k++) {
        int bx = k & 1, by = (k >> 1) & 1, bz = (k >> 2) & 1;
        int jx = min(max(ix + bx, 0), GRID - 1);
        int jy = min(max(iy + by, 0), GRID - 1);
        int jz = min(max(iz + bz, 0), GRID - 1);
        float w = (bx ? cwx : fwx) * (by ? cwy : fwy) * (bz ? cwz : fwz);
        unsigned cell = (((unsigned)pi * GRID + jz) * GRID + jy) * GRID + jx;
        g_cells[n * 8 + k] = cell;
        g_wts[n * 8 + k] = w;
        atomicAdd(&g_counts[cell], 1u);
    }
}

// ---------------------------------------------------------------------------
// K2: single-block exclusive scan of 16384 counts
// ---------------------------------------------------------------------------
__global__ void k_scan() {
    __shared__ unsigned part[512];
    int t = threadIdx.x;
    unsigned sum = 0;
    #pragma unroll 4
    for (int i = 0; i < 32; i++) sum += g_counts[t * 32 + i];
    part[t] = sum;
    __syncthreads();
    for (int off = 1; off < 512; off <<= 1) {
        unsigned v = 0;
        if (t >= off) v = part[t - off];
        __syncthreads();
        if (t >= off) part[t] += v;
        __syncthreads();
    }
    unsigned run = (t == 0) ? 0u : part[t - 1];
    #pragma unroll 4
    for (int i = 0; i < 32; i++) {
        int idx = t * 32 + i;
        g_offsets[idx] = run;
        g_cursor[idx] = run;
        run += g_counts[idx];
    }
    if (t == 511) g_offsets[NCELLS] = run;
}

// ---------------------------------------------------------------------------
// K3: scatter entries into cell-grouped order (+ sorted weights, counts reset)
// ---------------------------------------------------------------------------
__global__ void k_scatter() {
    int e = blockIdx.x * blockDim.x + threadIdx.x;
    if (e < NCELLS) g_counts[e] = 0u;
    if (e >= NENT) return;
    unsigned cell = g_cells[e];
    unsigned slot = atomicAdd(&g_cursor[cell], 1u);
    g_sorted[slot] = (unsigned)e;
    g_swts[slot] = g_wts[e];
}

// ---------------------------------------------------------------------------
// K4: fully pipelined per-cell GEMM.
//   - One CTA (128 thr) owns CPC=8 consecutive cells; batches of B=16 slots.
//   - y staging is a raw memcpy of xs rows (w applied in epilogue) done with
//     cp.async one batch ahead; entry ids/weights staged three batches ahead.
//     One commit-group per iteration; wait_group 1 keeps exactly the next
//     batch in flight -> global-load latency never blocks the FFMA2 stream.
//   - K (16KB)+bias double-buffered via cp.async.bulk + mbarrier, prefetched
//     one (nonempty) cell ahead.
//   - Tile: 2 slots x 4 cols per thread, packed FFMA2 (fma-pipe floor).
//   - Epilogue: red.global.add.v4.f32 straight into d_out.
// ---------------------------------------------------------------------------
#define KBYTES   (C_IN * C_OUT * 4)          // 16384
#define BBYTES   (C_OUT * 4)                 // 256
#define TXBYTES  (KBYTES + BBYTES)           // 16640

#define ADV(ci, bs) do { (bs) += B;                                           \
    while ((ci) < CPC && (bs) >= (int)(soff[(ci)+1] - soff[(ci)])) {          \
        (ci)++; (bs) = 0; } } while (0)

__global__ __launch_bounds__(128) void k_cell_gemm(
    const float* __restrict__ xs,
    const float* __restrict__ kernels,
    const float* __restrict__ biases,
    float* __restrict__ out) {

    __shared__ __align__(16) float ksm[2][C_IN * C_OUT];   // 32KB
    __shared__ __align__(16) float bsm[2][C_OUT];          // 512B
    __shared__ __align__(16) float ybuf[2][B][YROW];       // 8704B
    __shared__ unsigned ebuf[4][B];                        // 256B
    __shared__ float    wbuf[4][B];                        // 256B
    __shared__ unsigned soff[CPC + 1];
    __shared__ __align__(8) unsigned long long mbar_s[2];

    const int t  = threadIdx.x;
    const int fj = t & 15;           // 16 col groups of 4
    const int ei = t >> 4;           // 8 slot groups of 2
    const int yb = ei * 2;
    const int kb = fj * 4;
    const int cell0 = blockIdx.x * CPC;

    uint32_t mb0 = smem_u32(&mbar_s[0]);
    uint32_t mb1 = smem_u32(&mbar_s[1]);
    uint32_t kd0 = smem_u32(&ksm[0][0]);
    uint32_t kd1 = smem_u32(&ksm[1][0]);
    uint32_t bd0 = smem_u32(&bsm[0][0]);
    uint32_t bd1 = smem_u32(&bsm[1][0]);

    if (t <= CPC) soff[t] = g_offsets[cell0 + t];
    if (t == 0) { mbar_init(mb0, 1); mbar_init(mb1, 1); }
    __syncthreads();

    // compute cursor (batch b)
    int cci = 0, cbase = 0;
    while (cci < CPC && (int)(soff[cci + 1] - soff[cci]) == 0) cci++;
    if (cci == CPC) return;   // empty CTA

    // prologue: K for first nonempty cell into buf0
    if (t == 0) {
        mbar_expect_tx(mb0, TXBYTES);
        bulk_g2s(kd0, kernels + (size_t)(cell0 + cci) * (C_IN * C_OUT), KBYTES, mb0);
        bulk_g2s(bd0, biases  + (size_t)(cell0 + cci) * C_OUT,          BBYTES, mb0);
    }

    // cursor copies for batches 1..4
    int c1i = cci, c1b = cbase; ADV(c1i, c1b);
    int c2i = c1i, c2b = c1b;   ADV(c2i, c2b);
    int c3i = c2i, c3b = c2b;   ADV(c3i, c3b);
    int c4i = c3i, c4b = c3b;   ADV(c4i, c4b);

    // sync-load e/w for batches 0 and 1
    if (t < B) {
        int s0 = (int)soff[cci] + cbase;
        ebuf[0][t] = g_sorted[s0 + t];
        wbuf[0][t] = g_swts[s0 + t];
        if (c1i < CPC) {
            int s1 = (int)soff[c1i] + c1b;
            ebuf[1][t] = g_sorted[s1 + t];
            wbuf[1][t] = g_swts[s1 + t];
        }
    }
    __syncthreads();

    // group A: y[0] (from ebuf[0]) + e[2]
    {
        #pragma unroll
        for (int k = 0; k < 2; k++) {
            int idx = t + k * 128, row = idx >> 4, ch = idx & 15;
            unsigned e = ebuf[0][row];
            cp_async16(smem_u32(&ybuf[0][row][0]) + ch * 16,
                       xs + (size_t)(e >> 3) * C_IN + ch * 4);
        }
        if (c2i < CPC) {
            int s2 = (int)soff[c2i] + c2b;
            if (t < B)            cp_async4(smem_u32(&ebuf[2][t]),     g_sorted + s2 + t);
            else if (t < 2 * B)   cp_async4(smem_u32(&wbuf[2][t - B]), g_swts   + s2 + (t - B));
        }
        cp_commit();
    }
    // group B: y[1] (from ebuf[1]) + e[3]
    {
        if (c1i < CPC) {
            #pragma unroll
            for (int k = 0; k < 2; k++) {
                int idx = t + k * 128, row = idx >> 4, ch = idx & 15;
                unsigned e = ebuf[1][row];
                cp_async16(smem_u32(&ybuf[1][row][0]) + ch * 16,
                           xs + (size_t)(e >> 3) * C_IN + ch * 4);
            }
        }
        if (c3i < CPC) {
            int s3 = (int)soff[c3i] + c3b;
            if (t < B)            cp_async4(smem_u32(&ebuf[3][t]),     g_sorted + s3 + t);
            else if (t < 2 * B)   cp_async4(smem_u32(&wbuf[3][t - B]), g_swts   + s3 + (t - B));
        }
        cp_commit();
    }
    cp_wait1();        // group A complete: y[0], e[2]
    __syncthreads();

    unsigned kpar0 = 0, kpar1 = 0;
    int kq = -1, prev_ci = -1;
    int b = 0;
    int ici = c2i, icb = c2b;   // issue cursor (batch b+2)
    int eci = c4i, ecb = c4b;   // e cursor (batch b+4)

    while (cci < CPC) {
        int nent = (int)(soff[cci + 1] - soff[cci]);
        int nb = min(B, nent - cbase);
        bool newcell = (cci != prev_ci);
        prev_ci = cci;

        if (newcell) {
            kq++;
            if (t == 0) {
                int nc = cci + 1;
                while (nc < CPC && soff[nc + 1] == soff[nc]) nc++;
                if (nc < CPC) {
                    int nbuf = (kq + 1) & 1;
                    uint32_t mb = nbuf ? mb1 : mb0;
                    mbar_expect_tx(mb, TXBYTES);
                    bulk_g2s(nbuf ? kd1 : kd0,
                             kernels + (size_t)(cell0 + nc) * (C_IN * C_OUT), KBYTES, mb);
                    bulk_g2s(nbuf ? bd1 : bd0,
                             biases + (size_t)(cell0 + nc) * C_OUT, BBYTES, mb);
                }
            }
            if (kq & 1) { mbar_wait(mb1, kpar1); kpar1 ^= 1u; }
            else        { mbar_wait(mb0, kpar0); kpar0 ^= 1u; }
        }

        const int kbuf = kq & 1;
        const int ysel = b & 1;
        const int ring = b & 3;

        // ---- compute batch b (warps whose 4 slots are all padding skip) ----
        if (((t >> 5) << 2) < nb) {
            const float* kcur = ksm[kbuf];
            const float* bcur = bsm[kbuf];
            const float* y0p = &ybuf[ysel][yb][0];
            const float* y1p = &ybuf[ysel][yb + 1][0];
            unsigned long long a00 = 0, a01 = 0, a10 = 0, a11 = 0;

            #pragma unroll
            for (int cb = 0; cb < 16; cb++) {
                float4 ya = *(const float4*)(y0p + cb * 4);
                float4 yc = *(const float4*)(y1p + cb * 4);
                const float* kp = kcur + cb * 4 * C_OUT + kb;
                ulonglong2 k0 = *(const ulonglong2*)(kp);
                ulonglong2 k1 = *(const ulonglong2*)(kp + C_OUT);
                ulonglong2 k2 = *(const ulonglong2*)(kp + 2 * C_OUT);
                ulonglong2 k3 = *(const ulonglong2*)(kp + 3 * C_OUT);
                unsigned long long u, v;
                u = bcast2(ya.x); v = bcast2(yc.x);
                ffma2(a00, u, k0.x); ffma2(a01, u, k0.y);
                ffma2(a10, v, k0.x); ffma2(a11, v, k0.y);
                u = bcast2(ya.y); v = bcast2(yc.y);
                ffma2(a00, u, k1.x); ffma2(a01, u, k1.y);
                ffma2(a10, v, k1.x); ffma2(a11, v, k1.y);
                u = bcast2(ya.z); v = bcast2(yc.z);
                ffma2(a00, u, k2.x); ffma2(a01, u, k2.y);
                ffma2(a10, v, k2.x); ffma2(a11, v, k2.y);
                u = bcast2(ya.w); v = bcast2(yc.w);
                ffma2(a00, u, k3.x); ffma2(a01, u, k3.y);
                ffma2(a10, v, k3.x); ffma2(a11, v, k3.y);
            }

            float bx = bcur[kb], by = bcur[kb + 1], bz = bcur[kb + 2], bw = bcur[kb + 3];
            if (yb < nb) {
                unsigned e = ebuf[ring][yb];
                float w = wbuf[ring][yb];
                float2 lo = unpack2(a00), hi = unpack2(a01);
                float4 o = make_float4(w * (lo.x + bx), w * (lo.y + by),
                                       w * (hi.x + bz), w * (hi.y + bw));
                red_add_v4(out + (size_t)(e >> 3) * C_OUT + kb, o);
            }
            if (yb + 1 < nb) {
                unsigned e = ebuf[ring][yb + 1];
                float w = wbuf[ring][yb + 1];
                float2 lo = unpack2(a10), hi = unpack2(a11);
                float4 o = make_float4(w * (lo.x + bx), w * (lo.y + by),
                                       w * (hi.x + bz), w * (hi.y + bw));
                red_add_v4(out + (size_t)(e >> 3) * C_OUT + kb, o);
            }
        }
        __syncthreads();   // everyone done with ybuf[ysel], ebuf[ring]

        // ---- issue group b+2: y[b+2] into ybuf[ysel], e[b+4] into ring ----
        if (ici < CPC) {
            int iring = (b + 2) & 3;
            #pragma unroll
            for (int k = 0; k < 2; k++) {
                int idx = t + k * 128, row = idx >> 4, ch = idx & 15;
                unsigned e = ebuf[iring][row];
                cp_async16(smem_u32(&ybuf[ysel][row][0]) + ch * 16,
                           xs + (size_t)(e >> 3) * C_IN + ch * 4);
            }
        }
        if (eci < CPC) {
            int ering = (b + 4) & 3;   // == ring; e[b] is dead now
            int es = (int)soff[eci] + ecb;
            if (t < B)          cp_async4(smem_u32(&ebuf[ering][t]),     g_sorted + es + t);
            else if (t < 2 * B) cp_async4(smem_u32(&wbuf[ering][t - B]), g_swts   + es + (t - B));
        }
        cp_commit();
        cp_wait1();        // group b+1 complete: y[b+1], e[b+3]
        __syncthreads();

        ADV(cci, cbase);
        ADV(ici, icb);
        ADV(eci, ecb);
        b++;
    }
}

// ---------------------------------------------------------------------------
// Launcher (graph-capturable).  4 launches; gemm 4th (ncu capture slot).
// ---------------------------------------------------------------------------
extern "C" void kernel_launch(void* const* d_in, const int* in_sizes, int n_in,
                              void* d_out, int out_size) {
    const int*   pidx    = (const int*)  d_in[0];
    const float* pos     = (const float*)d_in[1];
    const float* xs      = (const float*)d_in[2];
    const float* kernels = (const float*)d_in[3];
    const float* biases  = (const float*)d_in[4];
    float* out = (float*)d_out;
    (void)in_sizes; (void)n_in; (void)out_size;

    k_prep<<<(NPTS + 255) / 256, 256>>>(pidx, pos, out);
    k_scan<<<1, 512>>>();
    k_scatter<<<(NENT + 255) / 256, 256>>>();
    k_cell_gemm<<<NGEMM, 128>>>(xs, kernels, biases, out);
}